// round 10
// baseline (speedup 1.0000x reference)
#include <cuda_runtime.h>
#include <math.h>

#define NPTS 384
#define HID 256
#define PT 16        // pairs per CTA
#define NT 128       // h per CTA
#define KC 32        // K chunk
#define NCHUNK (HID / KC)

// ---- strict fp32 (XLA fusion semantics: separate RN mul/add, no fma) ----
__device__ __forceinline__ float sq_ref(float x, float y, float z) {
    return __fadd_rn(__fadd_rn(__fmul_rn(x, x), __fmul_rn(y, y)), __fmul_rn(z, z));
}
__device__ __forceinline__ float dot_strict(float ax, float ay, float az,
                                            float bx, float by, float bz) {
    return __fadd_rn(__fadd_rn(__fmul_rn(ax, bx), __fmul_rn(ay, by)), __fmul_rn(az, bz));
}
__device__ __forceinline__ float dist_ref(float sqi, float sqm, float dotv) {
    float t1 = __fadd_rn(sqi, sqm);
    float t2 = __fmul_rn(2.0f, dotv);
    float d2 = __fsub_rn(t1, t2);
    return __fsqrt_rn(fmaxf(d2, 0.0f));
}
// XLA reduce starts from +0: a sum that collapsed to -0.0 becomes +0.0.
// (For any nonzero result this is exact/identity.) Bit-check so the compiler
// cannot fold it away.
__device__ __forceinline__ float fix_negzero(float v) {
    if (__float_as_uint(v) == 0x80000000u) v = 0.0f;
    return v;
}

// scratch: ref vectors (knn_point - point) per point, 3 neighbors x 3 dims
__device__ float g_ref[NPTS * 3 * 3];

// ---------------------------------------------------------------------------
// Kernel 1: 3-NN per point (neighbor sets proven robust to lattice choice).
// ---------------------------------------------------------------------------
__global__ void knn_kernel(const float* __restrict__ pts) {
    __shared__ float sp[NPTS * 3];
    int t = threadIdx.x;
    for (int k = t; k < NPTS * 3; k += blockDim.x) sp[k] = pts[k];
    __syncthreads();

    float px = sp[t * 3 + 0], py = sp[t * 3 + 1], pz = sp[t * 3 + 2];
    float sqi = sq_ref(px, py, pz);

    float b0 = 1e30f, b1 = 1e30f, b2 = 1e30f, b3 = 1e30f;
    int i0 = 0, i1 = 0, i2 = 0, i3 = 0;

    for (int m = 0; m < NPTS; m++) {
        float qx = sp[m * 3 + 0], qy = sp[m * 3 + 1], qz = sp[m * 3 + 2];
        float sqm = sq_ref(qx, qy, qz);
        float dotv = dot_strict(px, py, pz, qx, qy, qz);
        float d = dist_ref(sqi, sqm, dotv);
        if (d < b3) {
            if (d < b2) {
                b3 = b2; i3 = i2;
                if (d < b1) {
                    b2 = b1; i2 = i1;
                    if (d < b0) {
                        b1 = b0; i1 = i0;
                        b0 = d; i0 = m;
                    } else { b1 = d; i1 = m; }
                } else { b2 = d; i2 = m; }
            } else { b3 = d; i3 = m; }
        }
    }
    int nn[3] = { i1, i2, i3 };   // drop top-1 (self at dist 0)
#pragma unroll
    for (int k = 0; k < 3; k++) {
        int j = nn[k];
        g_ref[(t * 3 + k) * 3 + 0] = __fsub_rn(sp[j * 3 + 0], px);
        g_ref[(t * 3 + k) * 3 + 1] = __fsub_rn(sp[j * 3 + 1], py);
        g_ref[(t * 3 + k) * 3 + 2] = __fsub_rn(sp[j * 3 + 2], pz);
    }
}

// ---------------------------------------------------------------------------
// Kernel 2: fused (indices -> sinusoidal embedding -> GEMM -> max/add), fp32.
// ---------------------------------------------------------------------------
__global__ __launch_bounds__(256) void embed_kernel(
    const float* __restrict__ pts,
    const float* __restrict__ Wd, const float* __restrict__ bd,
    const float* __restrict__ Wa, const float* __restrict__ ba,
    float* __restrict__ out)
{
    __shared__ float xs[PT * 4];
    __shared__ float fdiv[HID / 2];
    __shared__ float As[KC * 64];
    __shared__ float Bsd[KC * 132];
    __shared__ float Bsa[KC * 132];

    int t = threadIdx.x;
    int pbase = blockIdx.x * PT;
    int hbase = blockIdx.y * NT;

    if (t < HID / 2) {
        const float c = -0.035977892078031965f;  // fp32(-ln(1e4)/256)
        fdiv[t] = expf(__fmul_rn((float)(2 * t), c));
    }

    if (t < PT) {
        int q = pbase + t;
        int i = q / NPTS;
        int m = q - i * NPTS;
        float pix = pts[i * 3 + 0], piy = pts[i * 3 + 1], piz = pts[i * 3 + 2];
        float pmx = pts[m * 3 + 0], pmy = pts[m * 3 + 1], pmz = pts[m * 3 + 2];
        float sqi = sq_ref(pix, piy, piz);
        float sqm = sq_ref(pmx, pmy, pmz);
        float dotv = dot_strict(pix, piy, piz, pmx, pmy, pmz);
        float dist = dist_ref(sqi, sqm, dotv);
        xs[t * 4 + 0] = __fdiv_rn(dist, 0.2f);
        float ax = __fsub_rn(pmx, pix), ay = __fsub_rn(pmy, piy), az = __fsub_rn(pmz, piz);
#pragma unroll
        for (int k = 0; k < 3; k++) {
            float rx = g_ref[(i * 3 + k) * 3 + 0];
            float ry = g_ref[(i * 3 + k) * 3 + 1];
            float rz = g_ref[(i * 3 + k) * 3 + 2];
            float cx = __fsub_rn(__fmul_rn(ry, az), __fmul_rn(rz, ay));
            float cy = __fsub_rn(__fmul_rn(rz, ax), __fmul_rn(rx, az));
            float cz = __fsub_rn(__fmul_rn(rx, ay), __fmul_rn(ry, ax));
            float sv = __fsqrt_rn(sq_ref(cx, cy, cz));
            // cos: XLA reduce-with-+0-init semantics. On the diagonal
            // (anc = +0 vector) the bare chain can yield -0.0 (all ref
            // components negative) -> atan2(0,-0)=pi, whereas XLA's
            // +0-seeded reduce yields +0 -> atan2(0,+0)=0.
            float cv = fix_negzero(dot_strict(rx, ry, rz, ax, ay, az));
            float ang = atan2f(sv, cv);
            xs[t * 4 + 1 + k] = __fmul_rn(ang, 3.8197186342054885f);
        }
    }
    __syncthreads();

    int row = t & 63;
    int jj0 = t >> 6;
    float x_row = xs[row];

    int tm = t & 15;
    int th = t >> 4;
    int hh = t >> 1;
    int cq = t & 1;

    float accd[8], a0[8], a1[8], a2[8];
#pragma unroll
    for (int e = 0; e < 8; e++) { accd[e] = 0.f; a0[e] = 0.f; a1[e] = 0.f; a2[e] = 0.f; }

    for (int ch = 0; ch < NCHUNK; ch++) {
        int kc = ch * KC;
        // embedding chunk
#pragma unroll
        for (int u = 0; u < 4; u++) {
            int jj = jj0 + 4 * u;
            float f = fdiv[(kc >> 1) + jj];
            float argv = __fmul_rn(x_row, f);
            float s, c;
            sincosf(argv, &s, &c);
            As[(2 * jj) * 64 + row] = s;
            As[(2 * jj + 1) * 64 + row] = c;
        }
        // W chunks transposed into smem
        const float* wdp = Wd + (hbase + hh) * HID + kc + cq * 16;
        const float* wap = Wa + (hbase + hh) * HID + kc + cq * 16;
#pragma unroll
        for (int u = 0; u < 4; u++) {
            float4 vd = *(const float4*)(wdp + 4 * u);
            float4 va = *(const float4*)(wap + 4 * u);
            int cc = cq * 16 + 4 * u;
            Bsd[(cc + 0) * 132 + hh] = vd.x;
            Bsd[(cc + 1) * 132 + hh] = vd.y;
            Bsd[(cc + 2) * 132 + hh] = vd.z;
            Bsd[(cc + 3) * 132 + hh] = vd.w;
            Bsa[(cc + 0) * 132 + hh] = va.x;
            Bsa[(cc + 1) * 132 + hh] = va.y;
            Bsa[(cc + 2) * 132 + hh] = va.z;
            Bsa[(cc + 3) * 132 + hh] = va.w;
        }
        __syncthreads();
#pragma unroll 8
        for (int c = 0; c < KC; c++) {
            float4 a  = *(const float4*)&As[c * 64 + tm * 4];
            float4 d0 = *(const float4*)&Bsd[c * 132 + th * 8];
            float4 d1 = *(const float4*)&Bsd[c * 132 + th * 8 + 4];
            float4 w0 = *(const float4*)&Bsa[c * 132 + th * 8];
            float4 w1 = *(const float4*)&Bsa[c * 132 + th * 8 + 4];
            accd[0] += a.x * d0.x; accd[1] += a.x * d0.y;
            accd[2] += a.x * d0.z; accd[3] += a.x * d0.w;
            accd[4] += a.x * d1.x; accd[5] += a.x * d1.y;
            accd[6] += a.x * d1.z; accd[7] += a.x * d1.w;
            a0[0] += a.y * w0.x; a0[1] += a.y * w0.y;
            a0[2] += a.y * w0.z; a0[3] += a.y * w0.w;
            a0[4] += a.y * w1.x; a0[5] += a.y * w1.y;
            a0[6] += a.y * w1.z; a0[7] += a.y * w1.w;
            a1[0] += a.z * w0.x; a1[1] += a.z * w0.y;
            a1[2] += a.z * w0.z; a1[3] += a.z * w0.w;
            a1[4] += a.z * w1.x; a1[5] += a.z * w1.y;
            a1[6] += a.z * w1.z; a1[7] += a.z * w1.w;
            a2[0] += a.w * w0.x; a2[1] += a.w * w0.y;
            a2[2] += a.w * w0.z; a2[3] += a.w * w0.w;
            a2[4] += a.w * w1.x; a2[5] += a.w * w1.y;
            a2[6] += a.w * w1.z; a2[7] += a.w * w1.w;
        }
        __syncthreads();
    }

    int q = pbase + tm;
    int h = hbase + th * 8;
    float4 bd0 = *(const float4*)(bd + h);
    float4 bd1 = *(const float4*)(bd + h + 4);
    float4 ba0 = *(const float4*)(ba + h);
    float4 ba1 = *(const float4*)(ba + h + 4);
    float4 o0, o1;
    o0.x = accd[0] + bd0.x + fmaxf(fmaxf(a0[0], a1[0]), a2[0]) + ba0.x;
    o0.y = accd[1] + bd0.y + fmaxf(fmaxf(a0[1], a1[1]), a2[1]) + ba0.y;
    o0.z = accd[2] + bd0.z + fmaxf(fmaxf(a0[2], a1[2]), a2[2]) + ba0.z;
    o0.w = accd[3] + bd0.w + fmaxf(fmaxf(a0[3], a1[3]), a2[3]) + ba0.w;
    o1.x = accd[4] + bd1.x + fmaxf(fmaxf(a0[4], a1[4]), a2[4]) + ba1.x;
    o1.y = accd[5] + bd1.y + fmaxf(fmaxf(a0[5], a1[5]), a2[5]) + ba1.y;
    o1.z = accd[6] + bd1.z + fmaxf(fmaxf(a0[6], a1[6]), a2[6]) + ba1.z;
    o1.w = accd[7] + bd1.w + fmaxf(fmaxf(a0[7], a1[7]), a2[7]) + ba1.w;
    *(float4*)(out + (size_t)q * HID + h) = o0;
    *(float4*)(out + (size_t)q * HID + h + 4) = o1;
}

extern "C" void kernel_launch(void* const* d_in, const int* in_sizes, int n_in,
                              void* d_out, int out_size) {
    (void)in_sizes; (void)n_in; (void)out_size;
    const float* pts = (const float*)d_in[0];
    const float* Wd  = (const float*)d_in[1];
    const float* bd  = (const float*)d_in[2];
    const float* Wa  = (const float*)d_in[3];
    const float* ba  = (const float*)d_in[4];
    float* out = (float*)d_out;

    knn_kernel<<<1, NPTS>>>(pts);
    dim3 grid(NPTS * NPTS / PT, HID / NT);   // (9216, 2)
    embed_kernel<<<grid, 256>>>(pts, Wd, bd, Wa, ba, out);
}

// round 13
// speedup vs baseline: 4.0536x; 4.0536x over previous
#include <cuda_runtime.h>
#include <math.h>
#include <stdint.h>

#define NPTS 384
#define HID 256
#define NPAIR (NPTS * NPTS)   // 147456
#define PT 64                 // pairs per CTA
#define NH 128                // h columns per CTA
#define KC 32                 // K chunk
#define NCH 8
#define AST 36                // A/B smem row stride (floats): frag reads conflict-free
#define DST 132               // D staging row stride (floats), 16B-aligned rows

// ---------------------------------------------------------------------------
// helpers
// ---------------------------------------------------------------------------
__device__ __forceinline__ float tf32_rna(float x) {
    unsigned r; asm("cvt.rna.tf32.f32 %0, %1;" : "=r"(r) : "f"(x));
    return __uint_as_float(r);
}
__device__ __forceinline__ float sq_ref(float x, float y, float z) {
    return __fadd_rn(__fadd_rn(__fmul_rn(x, x), __fmul_rn(y, y)), __fmul_rn(z, z));
}
__device__ __forceinline__ float dot_strict(float ax, float ay, float az,
                                            float bx, float by, float bz) {
    return __fadd_rn(__fadd_rn(__fmul_rn(ax, bx), __fmul_rn(ay, by)), __fmul_rn(az, bz));
}
__device__ __forceinline__ float dist_ref(float sqi, float sqm, float dotv) {
    float t1 = __fadd_rn(sqi, sqm);
    float t2 = __fmul_rn(2.0f, dotv);
    float d2 = __fsub_rn(t1, t2);
    return __fsqrt_rn(fmaxf(d2, 0.0f));
}
__device__ __forceinline__ float fix_negzero(float v) {
    if (__float_as_uint(v) == 0x80000000u) v = 0.0f;
    return v;
}

__device__ float g_ref[NPTS * 3 * 3];

// ---------------------------------------------------------------------------
// Kernel 1: 3-NN per point (unchanged from the passing R10 kernel)
// ---------------------------------------------------------------------------
__global__ void knn_kernel(const float* __restrict__ pts) {
    __shared__ float sp[NPTS * 3];
    int t = threadIdx.x;
    for (int k = t; k < NPTS * 3; k += blockDim.x) sp[k] = pts[k];
    __syncthreads();

    float px = sp[t * 3 + 0], py = sp[t * 3 + 1], pz = sp[t * 3 + 2];
    float sqi = sq_ref(px, py, pz);

    float b0 = 1e30f, b1 = 1e30f, b2 = 1e30f, b3 = 1e30f;
    int i0 = 0, i1 = 0, i2 = 0, i3 = 0;

    for (int m = 0; m < NPTS; m++) {
        float qx = sp[m * 3 + 0], qy = sp[m * 3 + 1], qz = sp[m * 3 + 2];
        float sqm = sq_ref(qx, qy, qz);
        float dotv = dot_strict(px, py, pz, qx, qy, qz);
        float d = dist_ref(sqi, sqm, dotv);
        if (d < b3) {
            if (d < b2) {
                b3 = b2; i3 = i2;
                if (d < b1) {
                    b2 = b1; i2 = i1;
                    if (d < b0) {
                        b1 = b0; i1 = i0;
                        b0 = d; i0 = m;
                    } else { b1 = d; i1 = m; }
                } else { b2 = d; i2 = m; }
            } else { b3 = d; i3 = m; }
        }
    }
    int nn[3] = { i1, i2, i3 };
#pragma unroll
    for (int k = 0; k < 3; k++) {
        int j = nn[k];
        g_ref[(t * 3 + k) * 3 + 0] = __fsub_rn(sp[j * 3 + 0], px);
        g_ref[(t * 3 + k) * 3 + 1] = __fsub_rn(sp[j * 3 + 1], py);
        g_ref[(t * 3 + k) * 3 + 2] = __fsub_rn(sp[j * 3 + 2], pz);
    }
}

// ---------------------------------------------------------------------------
// Kernel 2: fused embed + TF32 mma.sync GEMM + max/bias epilogue.
// CTA: 64 pairs x 128 h. M=256 rows src-major: rows src*64+p.
// 16 warps: wid -> (src=wid>>2, mseg=(wid>>1)&1, nseg=wid&1), warp tile m32 x n64.
// ---------------------------------------------------------------------------
__global__ __launch_bounds__(512, 1) void mma_kernel(
    const float* __restrict__ pts,
    const float* __restrict__ Wd, const float* __restrict__ bd,
    const float* __restrict__ Wa, const float* __restrict__ ba,
    float* __restrict__ out)
{
    extern __shared__ float sm[];
    float* As = sm;                   // [256][AST]
    float* Bs = sm + 256 * AST;       // [256][AST]: rows 0..127 Wd-half, 128..255 Wa-half
    float* Ds = sm;                   // [256][DST] (epilogue alias)
    __shared__ float xs[PT * 4];      // xs[p*4 + src]
    __shared__ float fdiv[HID / 2];
    __shared__ float sbd[NH], sba[NH];

    int t = threadIdx.x;
    int nh = blockIdx.x;
    int pbase = blockIdx.y * PT;

    if (t < HID / 2) {
        const float c = -0.035977892078031965f;  // fp32(-ln(1e4)/256)
        fdiv[t] = expf(__fmul_rn((float)(2 * t), c));
    }
    if (t < NH) { sbd[t] = bd[nh * NH + t]; sba[t] = ba[nh * NH + t]; }
    if (t < PT) {
        int q = pbase + t;
        int i = q / NPTS;
        int m = q - i * NPTS;
        float pix = pts[i * 3 + 0], piy = pts[i * 3 + 1], piz = pts[i * 3 + 2];
        float pmx = pts[m * 3 + 0], pmy = pts[m * 3 + 1], pmz = pts[m * 3 + 2];
        float sqi = sq_ref(pix, piy, piz);
        float sqm = sq_ref(pmx, pmy, pmz);
        float dotv = dot_strict(pix, piy, piz, pmx, pmy, pmz);
        float dist = dist_ref(sqi, sqm, dotv);
        xs[t * 4 + 0] = __fdiv_rn(dist, 0.2f);
        float ax = __fsub_rn(pmx, pix), ay = __fsub_rn(pmy, piy), az = __fsub_rn(pmz, piz);
#pragma unroll
        for (int k = 0; k < 3; k++) {
            float rx = g_ref[(i * 3 + k) * 3 + 0];
            float ry = g_ref[(i * 3 + k) * 3 + 1];
            float rz = g_ref[(i * 3 + k) * 3 + 2];
            float cx = __fsub_rn(__fmul_rn(ry, az), __fmul_rn(rz, ay));
            float cy = __fsub_rn(__fmul_rn(rz, ax), __fmul_rn(rx, az));
            float cz = __fsub_rn(__fmul_rn(rx, ay), __fmul_rn(ry, ax));
            float sv = __fsqrt_rn(sq_ref(cx, cy, cz));
            float cv = fix_negzero(dot_strict(rx, ry, rz, ax, ay, az));
            float ang = atan2f(sv, cv);
            xs[t * 4 + 1 + k] = __fmul_rn(ang, 3.8197186342054885f);
        }
    }
    __syncthreads();

    int wid = t >> 5, lane = t & 31;
    int src = wid >> 2, mseg = (wid >> 1) & 1, nseg = wid & 1;
    int g = lane >> 2, tig = lane & 3;
    int arow0 = src * 64 + mseg * 32;
    int brow = (src ? 128 : 0) + nseg * 64;

    // A producer mapping: lanes vary jl -> ~2-way STS conflicts only
    int jl = t & 15, rowg = t >> 4;    // rows rowg + 32u

    float acc[2][8][4];
#pragma unroll
    for (int a = 0; a < 2; a++)
#pragma unroll
        for (int b = 0; b < 8; b++)
#pragma unroll
            for (int cc = 0; cc < 4; cc++) acc[a][b][cc] = 0.0f;

    // register prefetch of B (next chunk's W tiles) to hide L2 latency
    float4 br[4];
#pragma unroll
    for (int u = 0; u < 4; u++) {
        int idx = t + 512 * u;
        int mm = idx >> 10, r = (idx >> 3) & 127, kq = idx & 7;
        const float* W = mm ? Wa : Wd;
        br[u] = *(const float4*)(W + (size_t)(nh * NH + r) * HID + kq * 4);
    }

    for (int ch = 0; ch < NCH; ch++) {
        // ---- produce A chunk (tf32 sin/cos) ----
        {
            float f = fdiv[ch * 16 + jl];
#pragma unroll
            for (int u = 0; u < 8; u++) {
                int row = rowg + 32 * u;
                float x = xs[((row & 63) << 2) | (row >> 6)];
                float arg = __fmul_rn(x, f);
                As[row * AST + 2 * jl]     = tf32_rna(__sinf(arg));
                As[row * AST + 2 * jl + 1] = tf32_rna(__cosf(arg));
            }
        }
        // ---- store prefetched B chunk (tf32) ----
#pragma unroll
        for (int u = 0; u < 4; u++) {
            int idx = t + 512 * u;
            int mm = idx >> 10, r = (idx >> 3) & 127, kq = idx & 7;
            float* d = Bs + (mm * 128 + r) * AST + kq * 4;
            d[0] = tf32_rna(br[u].x); d[1] = tf32_rna(br[u].y);
            d[2] = tf32_rna(br[u].z); d[3] = tf32_rna(br[u].w);
        }
        __syncthreads();
        // ---- issue next chunk's B loads (latency hidden by mma phase) ----
        if (ch + 1 < NCH) {
#pragma unroll
            for (int u = 0; u < 4; u++) {
                int idx = t + 512 * u;
                int mm = idx >> 10, r = (idx >> 3) & 127, kq = idx & 7;
                const float* W = mm ? Wa : Wd;
                br[u] = *(const float4*)(W + (size_t)(nh * NH + r) * HID
                                         + (ch + 1) * KC + kq * 4);
            }
        }
        // ---- mma phase: 4 k8 steps ----
#pragma unroll
        for (int ks = 0; ks < 4; ks++) {
            int kl = ks * 8;
            uint32_t afr[2][4];
#pragma unroll
            for (int mt = 0; mt < 2; mt++) {
                const float* ap = As + (arow0 + mt * 16 + g) * AST + kl + tig;
                afr[mt][0] = __float_as_uint(ap[0]);
                afr[mt][1] = __float_as_uint(ap[8 * AST]);
                afr[mt][2] = __float_as_uint(ap[4]);
                afr[mt][3] = __float_as_uint(ap[8 * AST + 4]);
            }
#pragma unroll
            for (int j = 0; j < 8; j++) {
                const float* bp = Bs + (brow + j * 8 + g) * AST + kl + tig;
                uint32_t b0 = __float_as_uint(bp[0]);
                uint32_t b1 = __float_as_uint(bp[4]);
#pragma unroll
                for (int mt = 0; mt < 2; mt++) {
                    asm volatile(
                        "mma.sync.aligned.m16n8k8.row.col.f32.tf32.tf32.f32 "
                        "{%0,%1,%2,%3}, {%4,%5,%6,%7}, {%8,%9}, {%0,%1,%2,%3};"
                        : "+f"(acc[mt][j][0]), "+f"(acc[mt][j][1]),
                          "+f"(acc[mt][j][2]), "+f"(acc[mt][j][3])
                        : "r"(afr[mt][0]), "r"(afr[mt][1]),
                          "r"(afr[mt][2]), "r"(afr[mt][3]),
                          "r"(b0), "r"(b1));
                }
            }
        }
        __syncthreads();
    }

    // ---- stage D to smem (aliases As/Bs; accumulators are in registers) ----
#pragma unroll
    for (int mt = 0; mt < 2; mt++) {
        int r0 = arow0 + mt * 16 + g;
#pragma unroll
        for (int j = 0; j < 8; j++) {
            int c = nseg * 64 + j * 8 + 2 * tig;
            *(float2*)&Ds[r0 * DST + c]       = make_float2(acc[mt][j][0], acc[mt][j][1]);
            *(float2*)&Ds[(r0 + 8) * DST + c] = make_float2(acc[mt][j][2], acc[mt][j][3]);
        }
    }
    __syncthreads();

    // ---- recombine: out = d + bd + max(a0,a1,a2) + ba ----
#pragma unroll
    for (int u = 0; u < 4; u++) {
        int idx = t + 512 * u;
        int p = idx >> 5, hq = idx & 31;
        float4 dv = *(float4*)&Ds[p * DST + 4 * hq];
        float4 a0 = *(float4*)&Ds[(64 + p) * DST + 4 * hq];
        float4 a1 = *(float4*)&Ds[(128 + p) * DST + 4 * hq];
        float4 a2 = *(float4*)&Ds[(192 + p) * DST + 4 * hq];
        float4 vd = *(float4*)&sbd[4 * hq];
        float4 va = *(float4*)&sba[4 * hq];
        float4 o;
        o.x = dv.x + vd.x + fmaxf(fmaxf(a0.x, a1.x), a2.x) + va.x;
        o.y = dv.y + vd.y + fmaxf(fmaxf(a0.y, a1.y), a2.y) + va.y;
        o.z = dv.z + vd.z + fmaxf(fmaxf(a0.z, a1.z), a2.z) + va.z;
        o.w = dv.w + vd.w + fmaxf(fmaxf(a0.w, a1.w), a2.w) + va.w;
        *(float4*)(out + (size_t)(pbase + p) * HID + nh * NH + 4 * hq) = o;
    }
}

// ---------------------------------------------------------------------------
#define SMEM_BYTES (256 * DST * 4)   // 135168: Ds; As+Bs (73728) alias within

extern "C" void kernel_launch(void* const* d_in, const int* in_sizes, int n_in,
                              void* d_out, int out_size) {
    (void)in_sizes; (void)n_in; (void)out_size;
    const float* pts = (const float*)d_in[0];
    const float* Wd  = (const float*)d_in[1];
    const float* bd  = (const float*)d_in[2];
    const float* Wa  = (const float*)d_in[3];
    const float* ba  = (const float*)d_in[4];
    float* out = (float*)d_out;

    cudaFuncSetAttribute(mma_kernel, cudaFuncAttributeMaxDynamicSharedMemorySize,
                         SMEM_BYTES);

    knn_kernel<<<1, NPTS>>>(pts);
    dim3 g(2, NPAIR / PT);   // (2 h-halves, 2304 pair tiles)
    mma_kernel<<<g, 512, SMEM_BYTES>>>(pts, Wd, bd, Wa, ba, out);
}

// round 15
// speedup vs baseline: 5.7192x; 1.4109x over previous
#include <cuda_runtime.h>
#include <cuda_fp16.h>
#include <math.h>
#include <stdint.h>

#define NPTS 384
#define HID 256
#define NPAIR (NPTS * NPTS)   // 147456
#define PT 64                 // pairs per CTA
#define NH 128                // h columns per CTA
#define NCH 8                 // K chunks of 32
#define DST 132               // epilogue staging row stride (floats)

// ---------------------------------------------------------------------------
__device__ __forceinline__ float sq_ref(float x, float y, float z) {
    return __fadd_rn(__fadd_rn(__fmul_rn(x, x), __fmul_rn(y, y)), __fmul_rn(z, z));
}
__device__ __forceinline__ float dot_strict(float ax, float ay, float az,
                                            float bx, float by, float bz) {
    return __fadd_rn(__fadd_rn(__fmul_rn(ax, bx), __fmul_rn(ay, by)), __fmul_rn(az, bz));
}
__device__ __forceinline__ float dist_ref(float sqi, float sqm, float dotv) {
    float t1 = __fadd_rn(sqi, sqm);
    float t2 = __fmul_rn(2.0f, dotv);
    float d2 = __fsub_rn(t1, t2);
    return __fsqrt_rn(fmaxf(d2, 0.0f));
}
__device__ __forceinline__ float fix_negzero(float v) {
    if (__float_as_uint(v) == 0x80000000u) v = 0.0f;
    return v;
}
__device__ __forceinline__ uint32_t smem_u32(const void* p) {
    uint32_t a;
    asm("{ .reg .u64 t; cvta.to.shared.u64 t, %1; cvt.u32.u64 %0, t; }" : "=r"(a) : "l"(p));
    return a;
}
#define LDMX4(r0, r1, r2, r3, addr) \
    asm volatile("ldmatrix.sync.aligned.m8n8.x4.shared.b16 {%0,%1,%2,%3}, [%4];" \
        : "=r"(r0), "=r"(r1), "=r"(r2), "=r"(r3) : "r"(addr))
#define MMA16816(c, a, b0, b1) \
    asm volatile("mma.sync.aligned.m16n8k16.row.col.f32.f16.f16.f32 " \
        "{%0,%1,%2,%3}, {%4,%5,%6,%7}, {%8,%9}, {%0,%1,%2,%3};" \
        : "+f"((c)[0]), "+f"((c)[1]), "+f"((c)[2]), "+f"((c)[3]) \
        : "r"((a)[0]), "r"((a)[1]), "r"((a)[2]), "r"((a)[3]), "r"(b0), "r"(b1))

__device__ float g_ref[NPTS * 3 * 3];
__device__ __half g_Wh[2 * 256 * 256];   // [0]=Wd, [1]=Wa, each [n][k] fp16

// ---------------------------------------------------------------------------
// Kernel 1: 3-NN per point (unchanged, passing since R10)
// ---------------------------------------------------------------------------
__global__ void knn_kernel(const float* __restrict__ pts) {
    __shared__ float sp[NPTS * 3];
    int t = threadIdx.x;
    for (int k = t; k < NPTS * 3; k += blockDim.x) sp[k] = pts[k];
    __syncthreads();

    float px = sp[t * 3 + 0], py = sp[t * 3 + 1], pz = sp[t * 3 + 2];
    float sqi = sq_ref(px, py, pz);

    float b0 = 1e30f, b1 = 1e30f, b2 = 1e30f, b3 = 1e30f;
    int i0 = 0, i1 = 0, i2 = 0, i3 = 0;

    for (int m = 0; m < NPTS; m++) {
        float qx = sp[m * 3 + 0], qy = sp[m * 3 + 1], qz = sp[m * 3 + 2];
        float sqm = sq_ref(qx, qy, qz);
        float dotv = dot_strict(px, py, pz, qx, qy, qz);
        float d = dist_ref(sqi, sqm, dotv);
        if (d < b3) {
            if (d < b2) {
                b3 = b2; i3 = i2;
                if (d < b1) {
                    b2 = b1; i2 = i1;
                    if (d < b0) {
                        b1 = b0; i1 = i0;
                        b0 = d; i0 = m;
                    } else { b1 = d; i1 = m; }
                } else { b2 = d; i2 = m; }
            } else { b3 = d; i3 = m; }
        }
    }
    int nn[3] = { i1, i2, i3 };
#pragma unroll
    for (int k = 0; k < 3; k++) {
        int j = nn[k];
        g_ref[(t * 3 + k) * 3 + 0] = __fsub_rn(sp[j * 3 + 0], px);
        g_ref[(t * 3 + k) * 3 + 1] = __fsub_rn(sp[j * 3 + 1], py);
        g_ref[(t * 3 + k) * 3 + 2] = __fsub_rn(sp[j * 3 + 2], pz);
    }
}

// ---------------------------------------------------------------------------
// Kernel 1b: convert W to fp16 once
// ---------------------------------------------------------------------------
__global__ void wconv_kernel(const float* __restrict__ Wd, const float* __restrict__ Wa) {
    int i = blockIdx.x * 256 + threadIdx.x;
    g_Wh[i] = __float2half(i < 65536 ? Wd[i] : Wa[i - 65536]);
}

// ---------------------------------------------------------------------------
// Kernel 2: fused embed + fp16 m16n8k16 mma GEMM + max/bias epilogue.
// CTA: 64 pairs x 128 h. M=256 rows src-major. 16 warps (src, mseg, nseg),
// warp tile m32 x n64. A/B staged fp16 in 64B rows with 16B-chunk XOR swizzle
// (chunk ^= (row&7)>>1) -> conflict-free ldmatrix. Double-buffered stages.
// ---------------------------------------------------------------------------
__global__ __launch_bounds__(512, 1) void mma_kernel(
    const float* __restrict__ pts,
    const float* __restrict__ bd, const float* __restrict__ ba,
    float* __restrict__ out)
{
    extern __shared__ char dsm[];
    // stage buffers: A[b] @ b*32768, B[b] @ b*32768 + 16384 (each 256 rows x 64B)
    float* Ds = (float*)dsm;          // epilogue staging alias [256][DST]
    __shared__ float xs[PT * 4];
    __shared__ float fdiv[HID / 2];
    __shared__ float sbd[NH], sba[NH];

    int t = threadIdx.x;
    int nh = blockIdx.x;
    int pbase = blockIdx.y * PT;

    if (t < HID / 2) {
        const float c = -0.035977892078031965f;  // fp32(-ln(1e4)/256)
        fdiv[t] = expf(__fmul_rn((float)(2 * t), c));
    }
    if (t < NH) { sbd[t] = bd[nh * NH + t]; sba[t] = ba[nh * NH + t]; }
    if (t < PT) {
        int q = pbase + t;
        int i = q / NPTS;
        int m = q - i * NPTS;
        float pix = pts[i * 3 + 0], piy = pts[i * 3 + 1], piz = pts[i * 3 + 2];
        float pmx = pts[m * 3 + 0], pmy = pts[m * 3 + 1], pmz = pts[m * 3 + 2];
        float sqi = sq_ref(pix, piy, piz);
        float sqm = sq_ref(pmx, pmy, pmz);
        float dotv = dot_strict(pix, piy, piz, pmx, pmy, pmz);
        float dist = dist_ref(sqi, sqm, dotv);
        xs[t * 4 + 0] = __fdiv_rn(dist, 0.2f);
        float ax = __fsub_rn(pmx, pix), ay = __fsub_rn(pmy, piy), az = __fsub_rn(pmz, piz);
#pragma unroll
        for (int k = 0; k < 3; k++) {
            float rx = g_ref[(i * 3 + k) * 3 + 0];
            float ry = g_ref[(i * 3 + k) * 3 + 1];
            float rz = g_ref[(i * 3 + k) * 3 + 2];
            float cx = __fsub_rn(__fmul_rn(ry, az), __fmul_rn(rz, ay));
            float cy = __fsub_rn(__fmul_rn(rz, ax), __fmul_rn(rx, az));
            float cz = __fsub_rn(__fmul_rn(rx, ay), __fmul_rn(ry, ax));
            float sv = __fsqrt_rn(sq_ref(cx, cy, cz));
            float cv = fix_negzero(dot_strict(rx, ry, rz, ax, ay, az));
            float ang = atan2f(sv, cv);
            xs[t * 4 + 1 + k] = __fmul_rn(ang, 3.8197186342054885f);
        }
    }
    __syncthreads();

    int wid = t >> 5, lane = t & 31;
    int src = wid >> 2, mseg = (wid >> 1) & 1, nseg = wid & 1;
    int g = lane >> 2, tig = lane & 3;
    int t4 = lane >> 3, r8 = lane & 7;
    int arow0 = src * 64 + mseg * 32;
    int brow = (src ? 128 : 0) + nseg * 64;
    int jl = t & 15, rowg = t >> 4;           // A-producer mapping
    int sw_rg = (rowg & 7) >> 1;              // producer swizzle term (row&7 const)

    float acc[2][8][4];
#pragma unroll
    for (int a = 0; a < 2; a++)
#pragma unroll
        for (int b = 0; b < 8; b++)
#pragma unroll
            for (int cc = 0; cc < 4; cc++) acc[a][b][cc] = 0.0f;

    // B global prefetch regs (fp16, 16B each)
    uint4 br[2];
    int brrow[2], brc[2];
#pragma unroll
    for (int u = 0; u < 2; u++) {
        int idx = t + 512 * u;
        brrow[u] = idx >> 2; brc[u] = idx & 3;
    }

    auto ldgB = [&](int ch) {
#pragma unroll
        for (int u = 0; u < 2; u++) {
            int row = brrow[u];
            int sel = row >> 7;
            int gn = (row & 127) + nh * 128;
            br[u] = *(const uint4*)(g_Wh + ((size_t)(sel * 256 + gn) * 256 + ch * 32 + brc[u] * 8));
        }
    };
    auto stsB = [&](char* Bb) {
#pragma unroll
        for (int u = 0; u < 2; u++) {
            int row = brrow[u], c = brc[u];
            *(uint4*)(Bb + row * 64 + ((c ^ ((row & 7) >> 1)) << 4)) = br[u];
        }
    };
    auto prodA = [&](int ch, char* Ab) {
        float f = fdiv[ch * 16 + jl];
        int coff = (((jl >> 2) ^ sw_rg) << 4) + ((jl & 3) << 2);
#pragma unroll
        for (int u = 0; u < 8; u++) {
            int row = rowg + 32 * u;
            float x = xs[((row & 63) << 2) | (row >> 6)];
            float arg = __fmul_rn(x, f);
            __half2 h = __floats2half2_rn(__sinf(arg), __cosf(arg));
            *(__half2*)(Ab + row * 64 + coff) = h;
        }
    };

    // prologue: stage chunk 0
    ldgB(0);
    prodA(0, dsm);
    stsB(dsm + 16384);
    __syncthreads();

    for (int ch = 0; ch < NCH; ch++) {
        char* cur = dsm + (ch & 1) * 32768;
        if (ch + 1 < NCH) {
            char* nxt = dsm + ((ch + 1) & 1) * 32768;
            ldgB(ch + 1);
            prodA(ch + 1, nxt);
            stsB(nxt + 16384);
        }
        uint32_t AbU = smem_u32(cur);
        uint32_t BbU = smem_u32(cur + 16384);
#pragma unroll
        for (int ks = 0; ks < 2; ks++) {
            uint32_t afr[2][4];
#pragma unroll
            for (int mt = 0; mt < 2; mt++) {
                int row = arow0 + mt * 16 + (t4 & 1) * 8 + r8;
                int c16 = ks * 2 + (t4 >> 1);
                uint32_t a = AbU + row * 64 + ((c16 ^ (r8 >> 1)) << 4);
                LDMX4(afr[mt][0], afr[mt][1], afr[mt][2], afr[mt][3], a);
            }
#pragma unroll
            for (int jp = 0; jp < 4; jp++) {
                int row = brow + jp * 16 + (t4 >> 1) * 8 + r8;
                int c16 = ks * 2 + (t4 & 1);
                uint32_t b = BbU + row * 64 + ((c16 ^ (r8 >> 1)) << 4);
                uint32_t bf0, bf1, bf2, bf3;
                LDMX4(bf0, bf1, bf2, bf3, b);
                MMA16816(acc[0][2 * jp],     afr[0], bf0, bf1);
                MMA16816(acc[0][2 * jp + 1], afr[0], bf2, bf3);
                MMA16816(acc[1][2 * jp],     afr[1], bf0, bf1);
                MMA16816(acc[1][2 * jp + 1], afr[1], bf2, bf3);
            }
        }
        __syncthreads();
    }

    // ---- stage D to smem (alias stage buffers) ----
#pragma unroll
    for (int mt = 0; mt < 2; mt++) {
        int r0 = arow0 + mt * 16 + g;
#pragma unroll
        for (int j = 0; j < 8; j++) {
            int c = nseg * 64 + j * 8 + 2 * tig;
            *(float2*)&Ds[r0 * DST + c]       = make_float2(acc[mt][j][0], acc[mt][j][1]);
            *(float2*)&Ds[(r0 + 8) * DST + c] = make_float2(acc[mt][j][2], acc[mt][j][3]);
        }
    }
    __syncthreads();

    // ---- recombine: out = d + bd + max(a0,a1,a2) + ba ----
#pragma unroll
    for (int u = 0; u < 4; u++) {
        int idx = t + 512 * u;
        int p = idx >> 5, hq = idx & 31;
        float4 dv = *(float4*)&Ds[p * DST + 4 * hq];
        float4 a0 = *(float4*)&Ds[(64 + p) * DST + 4 * hq];
        float4 a1 = *(float4*)&Ds[(128 + p) * DST + 4 * hq];
        float4 a2 = *(float4*)&Ds[(192 + p) * DST + 4 * hq];
        float4 vd = *(float4*)&sbd[4 * hq];
        float4 va = *(float4*)&sba[4 * hq];
        float4 o;
        o.x = dv.x + vd.x + fmaxf(fmaxf(a0.x, a1.x), a2.x) + va.x;
        o.y = dv.y + vd.y + fmaxf(fmaxf(a0.y, a1.y), a2.y) + va.y;
        o.z = dv.z + vd.z + fmaxf(fmaxf(a0.z, a1.z), a2.z) + va.z;
        o.w = dv.w + vd.w + fmaxf(fmaxf(a0.w, a1.w), a2.w) + va.w;
        *(float4*)(out + (size_t)(pbase + p) * HID + nh * NH + 4 * hq) = o;
    }
}

// ---------------------------------------------------------------------------
#define SMEM_BYTES (256 * DST * 4)   // 135168 >= 2x32KB stages

extern "C" void kernel_launch(void* const* d_in, const int* in_sizes, int n_in,
                              void* d_out, int out_size) {
    (void)in_sizes; (void)n_in; (void)out_size;
    const float* pts = (const float*)d_in[0];
    const float* Wd  = (const float*)d_in[1];
    const float* bd  = (const float*)d_in[2];
    const float* Wa  = (const float*)d_in[3];
    const float* ba  = (const float*)d_in[4];
    float* out = (float*)d_out;

    cudaFuncSetAttribute(mma_kernel, cudaFuncAttributeMaxDynamicSharedMemorySize,
                         SMEM_BYTES);

    knn_kernel<<<1, NPTS>>>(pts);
    wconv_kernel<<<512, 256>>>(Wd, Wa);
    dim3 g(2, NPAIR / PT);   // (2 h-halves, 2304 pair tiles)
    mma_kernel<<<g, 512, SMEM_BYTES>>>(pts, bd, ba, out);
}